// round 12
// baseline (speedup 1.0000x reference)
#include <cuda_runtime.h>

// FeatureExtractor_50165218017745  (R12: R11 + conflict-free vadd2 epilogue)
// Input : imgs_in [64, 3, 512, 512] float32 in [0,1)
// Output: [64, 96, 4, 4] float32
//
// R5/R11 base: parity-packed u16 privatized smem histograms (bank == lane
// in the hot loop), depth-1 LDG.128 prefetch with prologue overlap, 16 KB
// smem, 7 CTAs/SM, 1024 blocks = ONE wave; fused threadfence-reduction
// epilogue finalizes each batch in-overlap and resets scratch for replay.
// R12 delta: block reduction reads u32 words with a +bin lane shift
// (bank = (g*16+i+bin) mod 32, distinct per lane -> conflict-free) and
// accumulates halfword pairs via __vadd2: 16 clean LDS vs 32 conflicted.

#define BINS   32
#define BATCH  64
#define PARTS  4
#define NBLK   (BATCH * 4 * PARTS)   // 1024 blocks

__device__ unsigned g_counts[BATCH * 4 * BINS];  // zero-init; reset each run
__device__ unsigned g_done[BATCH];               // zero-init; reset each run

// bin = floor(32x) for x in [0,1): FFMA.RZ + 2^23 leaves floor(32x) in the
// low mantissa bits (exact for 0 <= 32x < 2^23).
__device__ __forceinline__ unsigned bin_of(float x) {
    return __float_as_uint(__fmaf_rz(x, 32.0f, 8388608.0f)) & 31u;
}

__device__ __forceinline__ void bump8(const float4& a, const float4& b,
                                      unsigned short* __restrict__ h) {
    h[bin_of(a.x) << 8] += 1u;
    h[bin_of(a.y) << 8] += 1u;
    h[bin_of(a.z) << 8] += 1u;
    h[bin_of(a.w) << 8] += 1u;
    h[bin_of(b.x) << 8] += 1u;
    h[bin_of(b.y) << 8] += 1u;
    h[bin_of(b.z) << 8] += 1u;
    h[bin_of(b.w) << 8] += 1u;
}

__device__ __forceinline__ const float4* row_ptr(const float* __restrict__ in,
                                                 int b, int qy, int qx, int ridx) {
    int c = ridx >> 8;        // channel 0..2
    int r = ridx & 255;       // row within quadrant
    return (const float4*)(in + (((((b * 3 + c) << 9) + (qy << 8) + r) << 9) + (qx << 8)));
}

__global__ __launch_bounds__(256, 7)
void fused_kernel(const float* __restrict__ in, float* __restrict__ out) {
    __shared__ unsigned short hist[BINS * 256];   // 16 KB, parity-packed
    __shared__ unsigned scratch[256 + 1];

    int bid  = blockIdx.x;                  // ((b*4 + q) * PARTS + part)
    int part = bid & (PARTS - 1);
    int q    = (bid >> 2) & 3;
    int b    = bid >> 4;
    int qy   = q >> 1;
    int qx   = q & 1;

    int tid  = threadIdx.x;
    int warp = tid >> 5;
    int lane = tid & 31;

    // Issue the first two rows' loads BEFORE touching smem: their DRAM
    // latency hides under the zeroing + barrier below.
    int ridx = part * 8 + warp;             // 0..31
    const float4* p0 = row_ptr(in, b, qy, qx, ridx);
    float4 v0 = p0[lane];
    float4 v1 = p0[lane + 32];
    const float4* p1 = row_ptr(in, b, qy, qx, ridx + 32);
    float4 w0 = p1[lane];
    float4 w1 = p1[lane + 32];

    // zero private histograms (4096 u32 words / 256 threads = 4 uint4 each)
    {
        uint4* z = (uint4*)hist;
        #pragma unroll
        for (int i = 0; i < 4; i++)
            z[tid + 256 * i] = make_uint4(0u, 0u, 0u, 0u);
    }
    __syncthreads();

    // Parity-packed slot: byte = bin*512 + (warp>>1)*128 + lane*4 + (warp&1)*2
    // -> bank = lane for every bin; bin b's 256 counters occupy u16 range
    // [b*256, b*256+256) (permuted), so the reduction is layout-agnostic.
    unsigned short* h = hist + ((warp >> 1) << 6) + (lane << 1) + (warp & 1);

    // 768 quadrant-rows (3 ch x 256); 32 warp-stripes -> 24 rows/warp.
    #pragma unroll 4
    for (int it = 0; it < 22; ++it) {
        ridx += 32;
        const float4* np = row_ptr(in, b, qy, qx, ridx + 32);
        float4 n0 = np[lane];
        float4 n1 = np[lane + 32];
        bump8(v0, v1, h);
        v0 = w0; v1 = w1;
        w0 = n0; w1 = n1;
    }
    bump8(v0, v1, h);
    bump8(w0, w1, h);
    __syncthreads();

    // Block reduction: bin = tid&31, g = tid>>5. Word local index
    // (g*16 + i + bin) & 127: the +bin shift makes bank distinct per lane
    // (conflict-free); mod-128 is a bijection so all 128 words of the bin
    // are covered. Each u32 = two u16 counters of the same bin -> vadd2
    // (max halfword sum 16*192 = 3072, no overflow), fold once.
    {
        const unsigned* hw = (const unsigned*)hist;
        int bin = tid & 31, g = tid >> 5;
        unsigned acc = 0;
        #pragma unroll
        for (int i = 0; i < 16; i++) {
            unsigned w = hw[bin * 128 + ((g * 16 + i + bin) & 127)];
            acc = __vadd2(acc, w);
        }
        scratch[tid] = (acc & 0xFFFFu) + (acc >> 16);
    }
    __syncthreads();
    if (tid < 32) {
        unsigned tot = 0;
        #pragma unroll
        for (int c = 0; c < 8; c++)
            tot += scratch[tid + 32 * c];
        atomicAdd(&g_counts[((b << 2) + q) * BINS + tid], tot);
    }

    // Release counts, then bump per-batch arrival counter (16 blocks/batch).
    __threadfence();
    __syncthreads();
    if (tid == 0)
        scratch[256] = atomicAdd(&g_done[b], 1u);
    __syncthreads();
    unsigned rank = scratch[256];
    if (rank != 4 * PARTS - 1) return;      // not the last block of batch b

    // ---- last block of batch b: finalize (overlapped with other batches) ----
    __threadfence();                        // acquire
    __syncthreads();

    float* s1  = (float*)hist;              // [128]: per-quadrant hist / 65536
    float* s0v = ((float*)hist) + 128;      // [32] : full-image hist / 262144

    if (tid < 128) {
        unsigned c = __ldcg(&g_counts[(b << 7) + tid]);
        s1[tid] = (float)c * (1.0f / 65536.0f);
        g_counts[(b << 7) + tid] = 0u;      // reset for next replay
    }
    __syncthreads();
    if (tid < 32)
        s0v[tid] = (s1[tid] + s1[32 + tid] + s1[64 + tid] + s1[96 + tid]) * 0.25f;
    if (tid == 0)
        g_done[b] = 0u;                     // reset for next replay
    __syncthreads();

    #pragma unroll
    for (int k = 0; k < 6; k++) {
        int idx  = tid + 256 * k;           // 0..1535
        int ch   = idx >> 4;
        int cell = idx & 15;                // y*4 + x
        float v = 0.0f;
        if (ch < 32) {
            v = s0v[ch];
        } else if (ch < 64) {
            int qq = ((cell >> 3) << 1) | ((cell >> 1) & 1);  // (y>>1)*2+(x>>1)
            v = s1[qq * BINS + (ch - 32)];
        }
        out[b * 1536 + idx] = v;
    }
}

extern "C" void kernel_launch(void* const* d_in, const int* in_sizes, int n_in,
                              void* d_out, int out_size) {
    (void)in_sizes; (void)n_in; (void)out_size;
    fused_kernel<<<NBLK, 256>>>((const float*)d_in[0], (float*)d_out);
}

// round 13
// speedup vs baseline: 1.0173x; 1.0173x over previous
#include <cuda_runtime.h>

// FeatureExtractor_50165218017745  (R13: R12 + L1-bypass (__ldcg) stream loads)
// Input : imgs_in [64, 3, 512, 512] float32 in [0,1)
// Output: [64, 96, 4, 4] float32
//
// R12 base: parity-packed u16 privatized smem histograms (bank == lane in
// the hot loop), depth-1 LDG.128 prefetch with prologue overlap, 16 KB smem,
// 7 CTAs/SM, 1024 blocks = ONE wave; conflict-free vadd2 block reduction;
// fused threadfence epilogue finalizes per-batch outputs in-overlap and
// resets scratch for graph replay.
// R13 delta: mainloop/prologue loads use __ldcg (L2-only, no L1 allocation)
// since the stream has zero reuse -- frees L1tex wavefronts for the smem RMW.

#define BINS   32
#define BATCH  64
#define PARTS  4
#define NBLK   (BATCH * 4 * PARTS)   // 1024 blocks

__device__ unsigned g_counts[BATCH * 4 * BINS];  // zero-init; reset each run
__device__ unsigned g_done[BATCH];               // zero-init; reset each run

// bin = floor(32x) for x in [0,1): FFMA.RZ + 2^23 leaves floor(32x) in the
// low mantissa bits (exact for 0 <= 32x < 2^23).
__device__ __forceinline__ unsigned bin_of(float x) {
    return __float_as_uint(__fmaf_rz(x, 32.0f, 8388608.0f)) & 31u;
}

__device__ __forceinline__ void bump8(const float4& a, const float4& b,
                                      unsigned short* __restrict__ h) {
    h[bin_of(a.x) << 8] += 1u;
    h[bin_of(a.y) << 8] += 1u;
    h[bin_of(a.z) << 8] += 1u;
    h[bin_of(a.w) << 8] += 1u;
    h[bin_of(b.x) << 8] += 1u;
    h[bin_of(b.y) << 8] += 1u;
    h[bin_of(b.z) << 8] += 1u;
    h[bin_of(b.w) << 8] += 1u;
}

__device__ __forceinline__ const float4* row_ptr(const float* __restrict__ in,
                                                 int b, int qy, int qx, int ridx) {
    int c = ridx >> 8;        // channel 0..2
    int r = ridx & 255;       // row within quadrant
    return (const float4*)(in + (((((b * 3 + c) << 9) + (qy << 8) + r) << 9) + (qx << 8)));
}

__global__ __launch_bounds__(256, 7)
void fused_kernel(const float* __restrict__ in, float* __restrict__ out) {
    __shared__ unsigned short hist[BINS * 256];   // 16 KB, parity-packed
    __shared__ unsigned scratch[256 + 1];

    int bid  = blockIdx.x;                  // ((b*4 + q) * PARTS + part)
    int part = bid & (PARTS - 1);
    int q    = (bid >> 2) & 3;
    int b    = bid >> 4;
    int qy   = q >> 1;
    int qx   = q & 1;

    int tid  = threadIdx.x;
    int warp = tid >> 5;
    int lane = tid & 31;

    // Issue the first two rows' loads BEFORE touching smem: their DRAM
    // latency hides under the zeroing + barrier below.
    int ridx = part * 8 + warp;             // 0..31
    const float4* p0 = row_ptr(in, b, qy, qx, ridx);
    float4 v0 = __ldcg(p0 + lane);
    float4 v1 = __ldcg(p0 + lane + 32);
    const float4* p1 = row_ptr(in, b, qy, qx, ridx + 32);
    float4 w0 = __ldcg(p1 + lane);
    float4 w1 = __ldcg(p1 + lane + 32);

    // zero private histograms (4096 u32 words / 256 threads = 4 uint4 each)
    {
        uint4* z = (uint4*)hist;
        #pragma unroll
        for (int i = 0; i < 4; i++)
            z[tid + 256 * i] = make_uint4(0u, 0u, 0u, 0u);
    }
    __syncthreads();

    // Parity-packed slot: byte = bin*512 + (warp>>1)*128 + lane*4 + (warp&1)*2
    // -> bank = lane for every bin; bin b's 256 counters occupy u16 range
    // [b*256, b*256+256) (permuted), so the reduction is layout-agnostic.
    unsigned short* h = hist + ((warp >> 1) << 6) + (lane << 1) + (warp & 1);

    // 768 quadrant-rows (3 ch x 256); 32 warp-stripes -> 24 rows/warp.
    #pragma unroll 4
    for (int it = 0; it < 22; ++it) {
        ridx += 32;
        const float4* np = row_ptr(in, b, qy, qx, ridx + 32);
        float4 n0 = __ldcg(np + lane);
        float4 n1 = __ldcg(np + lane + 32);
        bump8(v0, v1, h);
        v0 = w0; v1 = w1;
        w0 = n0; w1 = n1;
    }
    bump8(v0, v1, h);
    bump8(w0, w1, h);
    __syncthreads();

    // Block reduction: bin = tid&31, g = tid>>5. Word local index
    // (g*16 + i + bin) & 127: +bin shift -> bank distinct per lane
    // (conflict-free); mod-128 bijection covers all 128 words of the bin.
    // Each u32 = two u16 counters of the same bin -> vadd2 (max halfword
    // sum 16*192 = 3072, no overflow), fold once.
    {
        const unsigned* hw = (const unsigned*)hist;
        int bin = tid & 31, g = tid >> 5;
        unsigned acc = 0;
        #pragma unroll
        for (int i = 0; i < 16; i++) {
            unsigned w = hw[bin * 128 + ((g * 16 + i + bin) & 127)];
            acc = __vadd2(acc, w);
        }
        scratch[tid] = (acc & 0xFFFFu) + (acc >> 16);
    }
    __syncthreads();
    if (tid < 32) {
        unsigned tot = 0;
        #pragma unroll
        for (int c = 0; c < 8; c++)
            tot += scratch[tid + 32 * c];
        atomicAdd(&g_counts[((b << 2) + q) * BINS + tid], tot);
    }

    // Release counts, then bump per-batch arrival counter (16 blocks/batch).
    __threadfence();
    __syncthreads();
    if (tid == 0)
        scratch[256] = atomicAdd(&g_done[b], 1u);
    __syncthreads();
    unsigned rank = scratch[256];
    if (rank != 4 * PARTS - 1) return;      // not the last block of batch b

    // ---- last block of batch b: finalize (overlapped with other batches) ----
    __threadfence();                        // acquire
    __syncthreads();

    float* s1  = (float*)hist;              // [128]: per-quadrant hist / 65536
    float* s0v = ((float*)hist) + 128;      // [32] : full-image hist / 262144

    if (tid < 128) {
        unsigned c = __ldcg(&g_counts[(b << 7) + tid]);
        s1[tid] = (float)c * (1.0f / 65536.0f);
        g_counts[(b << 7) + tid] = 0u;      // reset for next replay
    }
    __syncthreads();
    if (tid < 32)
        s0v[tid] = (s1[tid] + s1[32 + tid] + s1[64 + tid] + s1[96 + tid]) * 0.25f;
    if (tid == 0)
        g_done[b] = 0u;                     // reset for next replay
    __syncthreads();

    #pragma unroll
    for (int k = 0; k < 6; k++) {
        int idx  = tid + 256 * k;           // 0..1535
        int ch   = idx >> 4;
        int cell = idx & 15;                // y*4 + x
        float v = 0.0f;
        if (ch < 32) {
            v = s0v[ch];
        } else if (ch < 64) {
            int qq = ((cell >> 3) << 1) | ((cell >> 1) & 1);  // (y>>1)*2+(x>>1)
            v = s1[qq * BINS + (ch - 32)];
        }
        out[b * 1536 + idx] = v;
    }
}

extern "C" void kernel_launch(void* const* d_in, const int* in_sizes, int n_in,
                              void* d_out, int out_size) {
    (void)in_sizes; (void)n_in; (void)out_size;
    fused_kernel<<<NBLK, 256>>>((const float*)d_in[0], (float*)d_out);
}